// round 1
// baseline (speedup 1.0000x reference)
#include <cuda_runtime.h>
#include <math.h>

#define DD 512
#define PP 36
#define PS 37          // padded SMEM row stride: conflict-free both row & column access
#define NTHREADS 512
#define EPSN 1e-12f
#define SCALE_CLS 7.0f

// SMEM layout (floats)
#define ST_OFF     0
#define SR_OFF     (DD*PS)                 // 18944
#define MT_OFF     (2*DD*PS)               // means test
#define MR_OFF     (MT_OFF + DD)
#define NT_OFF     (MR_OFF + DD)           // per-position norms (test)
#define NR_OFF     (NT_OFF + 40)
#define STE_OFF    (NR_OFF + 40)           // selection scores test
#define STR_OFF    (STE_OFF + 40)
#define WT_OFF     (STR_OFF + 40)          // fuse weights
#define WR_OFF     (WT_OFF + 40)
#define RED_OFF    (WR_OFF + 40)           // 64 floats reduction scratch
#define SMEM_FLOATS (RED_OFF + 64)
#define SMEM_BYTES  (SMEM_FLOATS * 4)      // ~156.9 KB

__device__ __forceinline__ float warp_sum(float v) {
#pragma unroll
    for (int o = 16; o > 0; o >>= 1) v += __shfl_down_sync(0xffffffffu, v, o);
    return v;
}

__global__ __launch_bounds__(NTHREADS, 1)
void fused_region_score_kernel(const float* __restrict__ ftrain,
                               const float* __restrict__ ftest,
                               const int*   __restrict__ Kp,
                               float* __restrict__ out,
                               int halfOut)
{
    extern __shared__ float sm[];
    float* st     = sm + ST_OFF;   // test tile  [D][PS]
    float* sr     = sm + SR_OFF;   // train tile [D][PS]
    float* mean_t = sm + MT_OFF;
    float* mean_r = sm + MR_OFF;
    float* nt     = sm + NT_OFF;
    float* nr     = sm + NR_OFF;
    float* s_te   = sm + STE_OFF;
    float* s_tr   = sm + STR_OFF;
    float* wt     = sm + WT_OFF;
    float* wr     = sm + WR_OFF;
    float* red    = sm + RED_OFF;

    const int g    = blockIdx.x;
    const int tid  = threadIdx.x;
    const int lane = tid & 31;
    const int wid  = tid >> 5;

    // ---------------- load tiles (single HBM pass), float4 coalesced --------
    // tile = D*P = 18432 floats = 4608 float4; rows are 36 floats (multiple of 4)
    const float4* gt = (const float4*)(ftest  + (size_t)g * (DD * PP));
    const float4* gr = (const float4*)(ftrain + (size_t)g * (DD * PP));
#pragma unroll
    for (int k = 0; k < 9; k++) {
        int j = tid + k * NTHREADS;      // 0..4607
        float4 a = gt[j];
        float4 b = gr[j];
        int d = j / 9;
        int p = (j - d * 9) * 4;
        int s = d * PS + p;
        st[s] = a.x; st[s+1] = a.y; st[s+2] = a.z; st[s+3] = a.w;
        sr[s] = b.x; sr[s+1] = b.y; sr[s+2] = b.z; sr[s+3] = b.w;
    }
    __syncthreads();

    // ---------------- stage A: spatial means per d + mean statistics --------
    {
        const int d = tid;
        const float* rt = st + d * PS;
        const float* rr = sr + d * PS;
        float sa = 0.f, sb = 0.f;
#pragma unroll
        for (int p = 0; p < PP; p++) { sa += rt[p]; sb += rr[p]; }
        float mt = sa * (1.0f / PP);
        float mr = sb * (1.0f / PP);
        mean_t[d] = mt;
        mean_r[d] = mr;
        float mm  = warp_sum(mt * mr);
        float mt2 = warp_sum(mt * mt);
        float mr2 = warp_sum(mr * mr);
        if (lane == 0) { red[wid] = mm; red[16 + wid] = mt2; red[32 + wid] = mr2; }
    }
    __syncthreads();
    if (wid == 0) {
        float a = (lane < 16) ? red[lane]      : 0.f;
        float b = (lane < 16) ? red[16 + lane] : 0.f;
        float c = (lane < 16) ? red[32 + lane] : 0.f;
        a = warp_sum(a); b = warp_sum(b); c = warp_sum(c);
        if (lane == 0) {
            // global score: 7 * <mt_n, mr_n>
            float denom = fmaxf(sqrtf(b), EPSN) * fmaxf(sqrtf(c), EPSN);
            out[g] = SCALE_CLS * a / denom;
        }
    }
    __syncthreads();   // mean arrays visible to stage B

    // ---------------- stage B: per-position norms + selection scores --------
    // warp w handles positions p = w, w+16, w+32; lane strides d by 32
    for (int p = wid; p < PP; p += 16) {
        float a2 = 0.f, b2 = 0.f, ta = 0.f, tb = 0.f;
#pragma unroll
        for (int i = 0; i < DD / 32; i++) {
            int d = lane + 32 * i;
            float a = st[d * PS + p];
            float b = sr[d * PS + p];
            a2 += a * a;
            b2 += b * b;
            ta += a * mean_r[d];   // ftest_scores direction (ft . mean_train)
            tb += b * mean_t[d];   // ftrain_scores direction (mean_test . fr)
        }
        a2 = warp_sum(a2); b2 = warp_sum(b2);
        ta = warp_sum(ta); tb = warp_sum(tb);
        if (lane == 0) {
            float na = fmaxf(sqrtf(a2), EPSN);
            float nb = fmaxf(sqrtf(b2), EPSN);
            nt[p] = na;
            nr[p] = nb;
            // constant positive factors (1/||mean||, 7) don't change ranking
            s_te[p] = ta / na;
            s_tr[p] = tb / nb;
        }
    }
    __syncthreads();

    // ---------------- stage C: top-K selection via rank counting ------------
    if (tid < PP) {
        const int K = *Kp;
        const int p = tid;
        float sv = s_te[p];
        int rank = 0;
#pragma unroll
        for (int q = 0; q < PP; q++) {
            float o = s_te[q];
            rank += (o > sv) || (o == sv && q < p);   // jax top_k tie-break: lower index wins
        }
        wt[p] = (rank < K) ? (1.0f / nt[p]) : 0.0f;

        sv = s_tr[p];
        rank = 0;
#pragma unroll
        for (int q = 0; q < PP; q++) {
            float o = s_tr[q];
            rank += (o > sv) || (o == sv && q < p);
        }
        wr[p] = (rank < K) ? (1.0f / nr[p]) : 0.0f;
    }
    __syncthreads();

    // ---------------- stage D: fused features + final score -----------------
    {
        const int d = tid;
        const float* rt = st + d * PS;
        const float* rr = sr + d * PS;
        float u = 0.f, v = 0.f;
#pragma unroll
        for (int p = 0; p < PP; p++) {
            u += rt[p] * wt[p];   // sum of selected normalized test positions (scale-free)
            v += rr[p] * wr[p];
        }
        float uu = warp_sum(u * u);
        float vv = warp_sum(v * v);
        float uv = warp_sum(u * v);
        if (lane == 0) { red[wid] = uv; red[16 + wid] = uu; red[32 + wid] = vv; }
    }
    __syncthreads();
    if (wid == 0) {
        float a = (lane < 16) ? red[lane]      : 0.f;  // uv
        float b = (lane < 16) ? red[16 + lane] : 0.f;  // uu
        float c = (lane < 16) ? red[32 + lane] : 0.f;  // vv
        a = warp_sum(a); b = warp_sum(b); c = warp_sum(c);
        if (lane == 0) {
            float denom = fmaxf(sqrtf(b), EPSN) * fmaxf(sqrtf(c), EPSN);
            out[halfOut + g] = SCALE_CLS * a / denom;
        }
    }
}

extern "C" void kernel_launch(void* const* d_in, const int* in_sizes, int n_in,
                              void* d_out, int out_size)
{
    const float* ftrain = (const float*)d_in[0];
    const float* ftest  = (const float*)d_in[1];
    const int*   Kp     = (const int*)d_in[2];
    float* out = (float*)d_out;

    const int groups  = in_sizes[0] / (DD * PP);   // 1500
    const int halfOut = out_size / 2;              // 1500

    cudaFuncSetAttribute(fused_region_score_kernel,
                         cudaFuncAttributeMaxDynamicSharedMemorySize, SMEM_BYTES);
    fused_region_score_kernel<<<groups, NTHREADS, SMEM_BYTES>>>(
        ftrain, ftest, Kp, out, halfOut);
}